// round 15
// baseline (speedup 1.0000x reference)
#include <cuda_runtime.h>
#include <cuda_fp16.h>

// Problem constants.
static constexpr int B_    = 4096;
static constexpr int NPRE  = 16384;
static constexpr int NPOST = 16384;
static constexpr int R_    = 32;
static constexpr int SPLITK = 32;
static constexpr int KRANGE = NPRE / SPLITK;   // 512
static constexpr int CHUNK  = 32;
static constexpr int NCHUNK = KRANGE / CHUNK;  // 16
static constexpr int MT256   = 16;             // 256-row m-tiles
static constexpr int UNITS_A = MT256 * SPLITK; // 512
static constexpr int UNITS_B = 1024;           // (16 mtiles x 2 bhalf) x 32 nstrip512
static constexpr int NA      = 148;            // producer CTAs
static constexpr int NB      = 148;            // consumer CTAs (pack U first)

// Scratch (__device__ globals; no allocations allowed).
__device__ float    g_Zpart[SPLITK * B_ * R_];  // 16 MB [split][b][r] fp32 (L2-resident)
__device__ unsigned g_Uth[(R_ / 2) * NPOST];    // 1 MB  U^T packed, [rp][n]
__device__ unsigned g_Zh[B_ * (R_ / 2)];        // 256 KB Z packed, [b][rp]
__device__ unsigned g_ctrA, g_ctrB, g_uctr;     // work-steal + U-pack counters
__device__ unsigned g_done[MT256];              // per-mtile split completion count
__device__ volatile unsigned g_ready[MT256];    // per-mtile Z-ready flag

// ---------------------------------------------------------------------------
// fp16 helpers + mma.sync m16n8k16 + ldmatrix (baseline PTX, plain sm_100).
// ---------------------------------------------------------------------------
__device__ __forceinline__ unsigned pack2h(float x0, float x1) {  // x0 -> low half
    __half2 t = __floats2half2_rn(x0, x1);
    return *reinterpret_cast<unsigned*>(&t);
}
__device__ __forceinline__ void mma16(float* d, const unsigned* a, const unsigned* b) {
    asm volatile(
        "mma.sync.aligned.m16n8k16.row.col.f32.f16.f16.f32 "
        "{%0,%1,%2,%3}, {%4,%5,%6,%7}, {%8,%9}, {%0,%1,%2,%3};"
        : "+f"(d[0]), "+f"(d[1]), "+f"(d[2]), "+f"(d[3])
        : "r"(a[0]), "r"(a[1]), "r"(a[2]), "r"(a[3]), "r"(b[0]), "r"(b[1]));
}
__device__ __forceinline__ void ldsm_x4(unsigned* r, unsigned addr) {
    asm volatile("ldmatrix.sync.aligned.m8n8.x4.shared.b16 {%0,%1,%2,%3}, [%4];"
                 : "=r"(r[0]), "=r"(r[1]), "=r"(r[2]), "=r"(r[3]) : "r"(addr));
}
__device__ __forceinline__ unsigned smem_u32(const void* p) {
    unsigned a;
    asm("{ .reg .u64 t; cvta.to.shared.u64 t, %1; cvt.u32.u64 %0, t; }"
        : "=r"(a) : "l"(p));
    return a;
}

// ---------------------------------------------------------------------------
// Tiny per-launch state reset.
// ---------------------------------------------------------------------------
__global__ void reset_state() {
    int t = threadIdx.x;
    if (t < MT256) { g_done[t] = 0; g_ready[t] = 0; }
    if (t == 16) g_ctrA = 0;
    if (t == 17) g_ctrB = 0;
    if (t == 18) g_uctr = 0;
}

// ---------------------------------------------------------------------------
// Fused persistent kernel with ROLE SPLIT for true read/write overlap:
//   CTAs [0, NA)   : phase-A producers (S @ V, split-K, inline reduction)
//   CTAs [NA, 296) : pack a U slice, then phase-B consumers (Z @ U^T)
// Producers join phase B after the A queue drains. All 296 CTAs co-resident
// (2/SM), so spin-waits always terminate.
// ---------------------------------------------------------------------------
struct SmemA { unsigned A[2][256 * 20]; unsigned Bv[2][16 * 36]; };  // 44.6 KB
struct SmemB { unsigned Z[128 * 20]; unsigned Uu[2][16 * 132]; };    // 26.5 KB

__global__ __launch_bounds__(256, 2) void fused(const float* __restrict__ S,
                                                const float* __restrict__ U,
                                                const float* __restrict__ V,
                                                float* __restrict__ Y) {
    __shared__ union { SmemA a; SmemB b; } sm;
    __shared__ unsigned s_u, s_red;

    const int tid = threadIdx.x, wid = tid >> 5, lane = tid & 31;
    const int gq = lane >> 2, tg = lane & 3;
    const int rowoff = ((lane >> 3) & 1) * 8 + (lane & 7);
    const int segoff = ((lane >> 4) & 1) * 16;   // bytes

    if (blockIdx.x < NA) {
        // ==================== Phase A: S @ V (producers) ====================
        for (;;) {
            if (tid == 0) s_u = atomicAdd(&g_ctrA, 1);
            __syncthreads();
            const unsigned u = s_u;
            if (u >= UNITS_A) break;
            const int m0 = (int)(u >> 5) * 256;     // mtile-major claim order
            const int k0 = (int)(u & 31) * KRANGE;
            const unsigned baseA = smem_u32(sm.a.A);

            float acc[2][4][4];
#pragma unroll
            for (int mt = 0; mt < 2; mt++)
#pragma unroll
                for (int nt = 0; nt < 4; nt++)
#pragma unroll
                    for (int q = 0; q < 4; q++) acc[mt][nt][q] = 0.f;

            float4 pS[8], pV0, pV1;
#pragma unroll
            for (int i = 0; i < 8; i++) {
                int idx = tid + i * 256, row = idx >> 3, kq = idx & 7;
                pS[i] = *reinterpret_cast<const float4*>(
                    &S[(size_t)(m0 + row) * NPRE + k0 + kq * 4]);
            }
            if (tid < 128) {   // V chunk [32 k][32 n] fp32, pack on commit
                int kpl = tid >> 3, n4 = (tid & 7) * 4;
                pV0 = *reinterpret_cast<const float4*>(&V[(size_t)(k0 + 2 * kpl) * R_ + n4]);
                pV1 = *reinterpret_cast<const float4*>(&V[(size_t)(k0 + 2 * kpl + 1) * R_ + n4]);
            }

            for (int c = 0; c < NCHUNK; c++) {
                const int buf = c & 1;
#pragma unroll
                for (int i = 0; i < 8; i++) {
                    int idx = tid + i * 256, row = idx >> 3, kq = idx & 7;
                    float4 v = pS[i];
                    *reinterpret_cast<uint2*>(&sm.a.A[buf][row * 20 + kq * 2]) =
                        make_uint2(pack2h(v.x, v.y), pack2h(v.z, v.w));
                }
                if (tid < 128) {
                    int kpl = tid >> 3, n4 = (tid & 7) * 4;
                    *reinterpret_cast<uint4*>(&sm.a.Bv[buf][kpl * 36 + n4]) =
                        make_uint4(pack2h(pV0.x, pV1.x), pack2h(pV0.y, pV1.y),
                                   pack2h(pV0.z, pV1.z), pack2h(pV0.w, pV1.w));
                }
                __syncthreads();

                if (c + 1 < NCHUNK) {
                    const int kn = k0 + (c + 1) * CHUNK;
#pragma unroll
                    for (int i = 0; i < 8; i++) {
                        int idx = tid + i * 256, row = idx >> 3, kq = idx & 7;
                        pS[i] = *reinterpret_cast<const float4*>(
                            &S[(size_t)(m0 + row) * NPRE + kn + kq * 4]);
                    }
                    if (tid < 128) {
                        int kpl = tid >> 3, n4 = (tid & 7) * 4;
                        pV0 = *reinterpret_cast<const float4*>(&V[(size_t)(kn + 2 * kpl) * R_ + n4]);
                        pV1 = *reinterpret_cast<const float4*>(&V[(size_t)(kn + 2 * kpl + 1) * R_ + n4]);
                    }
                }

                const unsigned bufA = baseA + buf * (256 * 20 * 4);
#pragma unroll
                for (int ks = 0; ks < 2; ks++) {
                    unsigned bf[4][2];
#pragma unroll
                    for (int nt = 0; nt < 4; nt++) {
                        bf[nt][0] = sm.a.Bv[buf][(ks * 8 + tg) * 36 + nt * 8 + gq];
                        bf[nt][1] = sm.a.Bv[buf][(ks * 8 + tg + 4) * 36 + nt * 8 + gq];
                    }
#pragma unroll
                    for (int mt = 0; mt < 2; mt++) {
                        const unsigned rb = (wid * 32 + mt * 16 + rowoff) * 80 + ks * 32 + segoff;
                        unsigned af[4];
                        ldsm_x4(af, bufA + rb);
#pragma unroll
                        for (int nt = 0; nt < 4; nt++)
                            mma16(acc[mt][nt], af, bf[nt]);
                    }
                }
            }

            // Partial epilogue into g_Zpart[split].
            float* out = &g_Zpart[(size_t)(u & 31) * B_ * R_];
#pragma unroll
            for (int mt = 0; mt < 2; mt++) {
                const int row = m0 + wid * 32 + mt * 16 + gq;
#pragma unroll
                for (int nt = 0; nt < 4; nt++) {
                    const int col = nt * 8 + tg * 2;
                    *reinterpret_cast<float2*>(&out[(size_t)row * R_ + col]) =
                        make_float2(acc[mt][nt][0], acc[mt][nt][1]);
                    *reinterpret_cast<float2*>(&out[(size_t)(row + 8) * R_ + col]) =
                        make_float2(acc[mt][nt][2], acc[mt][nt][3]);
                }
            }
            __threadfence();
            __syncthreads();
            if (tid == 0) {
                unsigned old = atomicAdd(&g_done[u >> 5], 1);
                s_red = (old == SPLITK - 1) ? 1u : 0u;
            }
            __syncthreads();
            if (s_red) {
                __threadfence();   // acquire side of producers' release
                const int mt = (int)(u >> 5);
#pragma unroll 4
                for (int j = 0; j < 16; j++) {
                    int w = tid + j * 256;                 // 0..4095
                    int b = mt * 256 + (w >> 4), rp = w & 15;
                    float2 s2 = make_float2(0.f, 0.f);
#pragma unroll
                    for (int sp = 0; sp < SPLITK; sp++) {
                        float2 v = *reinterpret_cast<const float2*>(
                            &g_Zpart[(size_t)sp * B_ * R_ + (size_t)b * R_ + 2 * rp]);
                        s2.x += v.x;
                        s2.y += v.y;
                    }
                    g_Zh[(size_t)b * 16 + rp] = pack2h(s2.x, s2.y);
                }
                __threadfence();
                __syncthreads();
                if (tid == 0) g_ready[mt] = 1;
            }
        }
    } else {
        // ==================== Consumers: pack U slice first ====================
        const int slice = (int)blockIdx.x - NA;            // 0..147
        const int nlo = slice * 111;
        const int nhi = min(nlo + 111, NPOST);
        for (int n = nlo + tid; n < nhi; n += 256) {
            float4 u[8];
#pragma unroll
            for (int i = 0; i < 8; i++)
                u[i] = *reinterpret_cast<const float4*>(&U[(size_t)n * R_ + i * 4]);
            const float* uf = reinterpret_cast<const float*>(u);
#pragma unroll
            for (int rp = 0; rp < 16; rp++)
                g_Uth[(size_t)rp * NPOST + n] = pack2h(uf[2 * rp], uf[2 * rp + 1]);
        }
        __threadfence();
        __syncthreads();
        if (tid == 0) atomicAdd(&g_uctr, 1);
    }

    // Wait for U fully packed (consumers arrive early; producers arrive late).
    while (*(volatile unsigned*)&g_uctr != NB) __nanosleep(64);
    __threadfence();

    // ======================== Phase B: Z @ U^T ========================
    const int wm = wid >> 2, wn = wid & 3;
    const unsigned baseZ = smem_u32(sm.b.Z);
    for (;;) {
        if (tid == 0) s_u = atomicAdd(&g_ctrB, 1);
        __syncthreads();
        const unsigned t = s_u;
        if (t >= UNITS_B) break;
        const int m256 = (int)(t >> 6), rem = (int)(t & 63);
        const int b0    = (m256 * 2 + (rem & 1)) * 128;
        const int nbase = (rem >> 1) * 512;

        while (g_ready[m256] == 0) __nanosleep(128);
        __threadfence();

        uint4 pU[2];
#pragma unroll
        for (int p = 0; p < 2; p++) {
            int idx = tid + p * 256, rp = idx >> 5, n4 = (idx & 31) * 4;
            pU[p] = *reinterpret_cast<const uint4*>(&g_Uth[(size_t)rp * NPOST + nbase + n4]);
        }
#pragma unroll
        for (int p = 0; p < 2; p++) {
            int idx = tid + p * 256, row = idx >> 2, c4 = (idx & 3) * 4;
            *reinterpret_cast<uint4*>(&sm.b.Z[row * 20 + c4]) =
                *reinterpret_cast<const uint4*>(&g_Zh[(size_t)(b0 + row) * 16 + c4]);
        }

        for (int st = 0; st < 4; st++) {
            const int buf = st & 1;
            const int n0 = nbase + st * 128;
#pragma unroll
            for (int p = 0; p < 2; p++) {
                int idx = tid + p * 256, rp = idx >> 5, n4 = (idx & 31) * 4;
                *reinterpret_cast<uint4*>(&sm.b.Uu[buf][rp * 132 + n4]) = pU[p];
            }
            __syncthreads();

            if (st + 1 < 4) {
#pragma unroll
                for (int p = 0; p < 2; p++) {
                    int idx = tid + p * 256, rp = idx >> 5, n4 = (idx & 31) * 4;
                    pU[p] = *reinterpret_cast<const uint4*>(
                        &g_Uth[(size_t)rp * NPOST + nbase + (st + 1) * 128 + n4]);
                }
            }

            float acc[4][4][4];
#pragma unroll
            for (int mt = 0; mt < 4; mt++)
#pragma unroll
                for (int nt = 0; nt < 4; nt++)
#pragma unroll
                    for (int q = 0; q < 4; q++) acc[mt][nt][q] = 0.f;

#pragma unroll
            for (int ks = 0; ks < 2; ks++) {
                unsigned bf[4][2];
#pragma unroll
                for (int nt = 0; nt < 4; nt++) {
                    const int nc = wn * 32 + nt * 8 + gq;
                    bf[nt][0] = sm.b.Uu[buf][(ks * 8 + tg) * 132 + nc];
                    bf[nt][1] = sm.b.Uu[buf][(ks * 8 + tg + 4) * 132 + nc];
                }
#pragma unroll
                for (int mt = 0; mt < 4; mt++) {
                    const unsigned rb = (wm * 64 + mt * 16 + rowoff) * 80 + ks * 32 + segoff;
                    unsigned af[4];
                    ldsm_x4(af, baseZ + rb);
#pragma unroll
                    for (int nt = 0; nt < 4; nt++)
                        mma16(acc[mt][nt], af, bf[nt]);
                }
            }

#pragma unroll
            for (int mt = 0; mt < 4; mt++) {
                const int row = b0 + wm * 64 + mt * 16 + gq;
#pragma unroll
                for (int nt = 0; nt < 4; nt++) {
                    const int col = n0 + wn * 32 + nt * 8 + tg * 2;
                    *reinterpret_cast<float2*>(&Y[(size_t)row * NPOST + col]) =
                        make_float2(acc[mt][nt][0], acc[mt][nt][1]);
                    *reinterpret_cast<float2*>(&Y[(size_t)(row + 8) * NPOST + col]) =
                        make_float2(acc[mt][nt][2], acc[mt][nt][3]);
                }
            }
            __syncthreads();   // subtile buffer handoff / tile boundary
        }
    }
}

// ---------------------------------------------------------------------------
// Entry point. Inputs: spikes, U, V, mask_* (masks unused by the reference).
// ---------------------------------------------------------------------------
extern "C" void kernel_launch(void* const* d_in, const int* in_sizes, int n_in,
                              void* d_out, int out_size) {
    const float* spikes = (const float*)d_in[0];
    const float* U      = (const float*)d_in[1];
    const float* V      = (const float*)d_in[2];
    float* Y            = (float*)d_out;

    reset_state<<<1, 32>>>();
    fused<<<NA + NB, 256>>>(spikes, U, V, Y);   // fully co-resident (2 CTAs/SM)
}

// round 17
// speedup vs baseline: 1.1743x; 1.1743x over previous
#include <cuda_runtime.h>
#include <cuda_fp16.h>

// Problem constants.
static constexpr int B_    = 4096;
static constexpr int NPRE  = 16384;
static constexpr int NPOST = 16384;
static constexpr int R_    = 32;
static constexpr int SPLITK = 32;
static constexpr int KRANGE = NPRE / SPLITK;   // 512
static constexpr int CHUNK  = 32;
static constexpr int NCHUNK = KRANGE / CHUNK;  // 16
static constexpr int MT256  = 16;              // 256-row m-tiles

// Scratch (__device__ globals; no allocations allowed).
__device__ float    g_Zpart[SPLITK * B_ * R_];  // 16 MB [split][b][r] fp32 (L2-resident)
__device__ unsigned g_Uth[(R_ / 2) * NPOST];    // 1 MB  U^T packed f16x2 (pairs along r), [rp][n]
__device__ unsigned g_Zh[B_ * (R_ / 2)];        // 256 KB Z packed, [b][rp]
__device__ unsigned g_done[MT256];              // per-mtile split completion count

// ---------------------------------------------------------------------------
// fp16 helpers + mma.sync m16n8k16 + ldmatrix (baseline PTX, plain sm_100).
// ---------------------------------------------------------------------------
__device__ __forceinline__ unsigned pack2h(float x0, float x1) {  // x0 -> low half
    __half2 t = __floats2half2_rn(x0, x1);
    return *reinterpret_cast<unsigned*>(&t);
}
__device__ __forceinline__ void mma16(float* d, const unsigned* a, const unsigned* b) {
    asm volatile(
        "mma.sync.aligned.m16n8k16.row.col.f32.f16.f16.f32 "
        "{%0,%1,%2,%3}, {%4,%5,%6,%7}, {%8,%9}, {%0,%1,%2,%3};"
        : "+f"(d[0]), "+f"(d[1]), "+f"(d[2]), "+f"(d[3])
        : "r"(a[0]), "r"(a[1]), "r"(a[2]), "r"(a[3]), "r"(b[0]), "r"(b[1]));
}
__device__ __forceinline__ void ldsm_x4(unsigned* r, unsigned addr) {
    asm volatile("ldmatrix.sync.aligned.m8n8.x4.shared.b16 {%0,%1,%2,%3}, [%4];"
                 : "=r"(r[0]), "=r"(r[1]), "=r"(r[2]), "=r"(r[3]) : "r"(addr));
}
__device__ __forceinline__ unsigned smem_u32(const void* p) {
    unsigned a;
    asm("{ .reg .u64 t; cvta.to.shared.u64 t, %1; cvt.u32.u64 %0, t; }"
        : "=r"(a) : "l"(p));
    return a;
}

// ---------------------------------------------------------------------------
// prepU (blocks 0..63) + per-launch state reset (block 64).
// ---------------------------------------------------------------------------
__global__ void prepU(const float* __restrict__ U) {
    if (blockIdx.x < 64) {
        int n = blockIdx.x * 256 + threadIdx.x;  // 0..NPOST-1
        float4 u[8];
#pragma unroll
        for (int i = 0; i < 8; i++)
            u[i] = *reinterpret_cast<const float4*>(&U[(size_t)n * R_ + i * 4]);
        const float* uf = reinterpret_cast<const float*>(u);
#pragma unroll
        for (int rp = 0; rp < 16; rp++)
            g_Uth[(size_t)rp * NPOST + n] = pack2h(uf[2 * rp], uf[2 * rp + 1]);
    } else {
        if (threadIdx.x < MT256) g_done[threadIdx.x] = 0;
    }
}

// ---------------------------------------------------------------------------
// GEMM1: Zpart[split] = S[:, range] @ V[range, :], V packed fp32->f16 on the
// fly; the 32nd finisher of each mtile inline-reduces its splits (L2-hot) and
// packs fp16 Z. Tile 256 rows x 32 n, 256 threads, double-buffered smem.
// Grid (split, mtile): mtile 0's CTAs launch first -> early reductions overlap.
// ---------------------------------------------------------------------------
__global__ __launch_bounds__(256) void gemmA(const float* __restrict__ S,
                                             const float* __restrict__ V) {
    __shared__ unsigned sA[2][256 * 20];   // 2 x 20 KB
    __shared__ unsigned sB[2][16 * 36];    // 2 x 2.25 KB
    __shared__ unsigned s_red;

    const int tid = threadIdx.x, wid = tid >> 5, lane = tid & 31;
    const int gq = lane >> 2, tg = lane & 3;
    const int split = blockIdx.x;           // 0..31
    const int mtile = blockIdx.y;           // 0..15
    const int m0 = mtile * 256;
    const int k0 = split * KRANGE;

    const int rowoff = ((lane >> 3) & 1) * 8 + (lane & 7);
    const int segoff = ((lane >> 4) & 1) * 16;   // bytes
    const unsigned baseA = smem_u32(sA);

    float acc[2][4][4];
#pragma unroll
    for (int mt = 0; mt < 2; mt++)
#pragma unroll
        for (int nt = 0; nt < 4; nt++)
#pragma unroll
            for (int q = 0; q < 4; q++) acc[mt][nt][q] = 0.f;

    // Prefetch chunk 0 (S fp32; V fp32 pair rows, packed at commit).
    float4 pS[8], pV0, pV1;
#pragma unroll
    for (int i = 0; i < 8; i++) {
        int idx = tid + i * 256, row = idx >> 3, kq = idx & 7;
        pS[i] = *reinterpret_cast<const float4*>(
            &S[(size_t)(m0 + row) * NPRE + k0 + kq * 4]);
    }
    if (tid < 128) {
        int kpl = tid >> 3, n4 = (tid & 7) * 4;
        pV0 = *reinterpret_cast<const float4*>(&V[(size_t)(k0 + 2 * kpl) * R_ + n4]);
        pV1 = *reinterpret_cast<const float4*>(&V[(size_t)(k0 + 2 * kpl + 1) * R_ + n4]);
    }

    for (int c = 0; c < NCHUNK; c++) {
        const int buf = c & 1;
#pragma unroll
        for (int i = 0; i < 8; i++) {
            int idx = tid + i * 256, row = idx >> 3, kq = idx & 7;
            float4 v = pS[i];
            *reinterpret_cast<uint2*>(&sA[buf][row * 20 + kq * 2]) =
                make_uint2(pack2h(v.x, v.y), pack2h(v.z, v.w));
        }
        if (tid < 128) {
            int kpl = tid >> 3, n4 = (tid & 7) * 4;
            *reinterpret_cast<uint4*>(&sB[buf][kpl * 36 + n4]) =
                make_uint4(pack2h(pV0.x, pV1.x), pack2h(pV0.y, pV1.y),
                           pack2h(pV0.z, pV1.z), pack2h(pV0.w, pV1.w));
        }
        __syncthreads();

        if (c + 1 < NCHUNK) {
            const int kn = k0 + (c + 1) * CHUNK;
#pragma unroll
            for (int i = 0; i < 8; i++) {
                int idx = tid + i * 256, row = idx >> 3, kq = idx & 7;
                pS[i] = *reinterpret_cast<const float4*>(
                    &S[(size_t)(m0 + row) * NPRE + kn + kq * 4]);
            }
            if (tid < 128) {
                int kpl = tid >> 3, n4 = (tid & 7) * 4;
                pV0 = *reinterpret_cast<const float4*>(&V[(size_t)(kn + 2 * kpl) * R_ + n4]);
                pV1 = *reinterpret_cast<const float4*>(&V[(size_t)(kn + 2 * kpl + 1) * R_ + n4]);
            }
        }

        const unsigned bufA = baseA + buf * (256 * 20 * 4);
#pragma unroll
        for (int ks = 0; ks < 2; ks++) {
            unsigned bf[4][2];
#pragma unroll
            for (int nt = 0; nt < 4; nt++) {
                bf[nt][0] = sB[buf][(ks * 8 + tg) * 36 + nt * 8 + gq];
                bf[nt][1] = sB[buf][(ks * 8 + tg + 4) * 36 + nt * 8 + gq];
            }
#pragma unroll
            for (int mt = 0; mt < 2; mt++) {
                const unsigned rb = (wid * 32 + mt * 16 + rowoff) * 80 + ks * 32 + segoff;
                unsigned af[4];
                ldsm_x4(af, bufA + rb);
#pragma unroll
                for (int nt = 0; nt < 4; nt++)
                    mma16(acc[mt][nt], af, bf[nt]);
            }
        }
    }

    // Partial epilogue into g_Zpart[split].
    float* out = &g_Zpart[(size_t)split * B_ * R_];
#pragma unroll
    for (int mt = 0; mt < 2; mt++) {
        const int row = m0 + wid * 32 + mt * 16 + gq;
#pragma unroll
        for (int nt = 0; nt < 4; nt++) {
            const int col = nt * 8 + tg * 2;
            *reinterpret_cast<float2*>(&out[(size_t)row * R_ + col]) =
                make_float2(acc[mt][nt][0], acc[mt][nt][1]);
            *reinterpret_cast<float2*>(&out[(size_t)(row + 8) * R_ + col]) =
                make_float2(acc[mt][nt][2], acc[mt][nt][3]);
        }
    }
    __threadfence();            // release: partials before counter
    __syncthreads();
    if (tid == 0) {
        unsigned old = atomicAdd(&g_done[mtile], 1);
        s_red = (old == SPLITK - 1) ? 1u : 0u;
    }
    __syncthreads();
    if (s_red) {
        __threadfence();        // acquire: pair with producers' release
        // Reduce this mtile's 32 partials (L2-hot) and pack fp16 Z.
        // Item = (row, rp4): 256 rows x 8 float4 groups = 2048 items, 8/thread.
        // (R16 bug: covered only 4 groups -> half of each Z row was garbage.)
#pragma unroll
        for (int j = 0; j < 8; j++) {
            int w = tid + j * 256;            // 0..2047
            int b = m0 + (w >> 3), rp4 = w & 7;
            float4 s4 = make_float4(0.f, 0.f, 0.f, 0.f);
#pragma unroll
            for (int sp = 0; sp < SPLITK; sp++) {
                float4 v = *reinterpret_cast<const float4*>(
                    &g_Zpart[(size_t)sp * B_ * R_ + (size_t)b * R_ + rp4 * 4]);
                s4.x += v.x; s4.y += v.y; s4.z += v.z; s4.w += v.w;
            }
            *reinterpret_cast<uint2*>(&g_Zh[(size_t)b * 16 + rp4 * 2]) =
                make_uint2(pack2h(s4.x, s4.y), pack2h(s4.z, s4.w));
        }
    }
}

// ---------------------------------------------------------------------------
// GEMM2 (verbatim R11 best): Y = Z @ U^T. CTA: 128-b tile x four 128-n
// subtiles; Z resident, U double-buffered; stores overlap next staging.
// ---------------------------------------------------------------------------
__global__ __launch_bounds__(256) void gemmB(float* __restrict__ Y) {
    __shared__ unsigned sZ[128 * 20];      // 10 KB, loaded once
    __shared__ unsigned sU[2][16 * 132];   // 2 x 8.25 KB

    const int tid = threadIdx.x, wid = tid >> 5, lane = tid & 31;
    const int gq = lane >> 2, tg = lane & 3;
    const int wm = wid >> 2, wn = wid & 3;
    const int nbase = blockIdx.x * 512;
    const int b0    = blockIdx.y * 128;

    const int rowoff = ((lane >> 3) & 1) * 8 + (lane & 7);
    const int segoff = ((lane >> 4) & 1) * 16;
    const unsigned baseZ = smem_u32(sZ);

    uint4 pU[2];
#pragma unroll
    for (int p = 0; p < 2; p++) {
        int idx = tid + p * 256, rp = idx >> 5, n4 = (idx & 31) * 4;
        pU[p] = *reinterpret_cast<const uint4*>(&g_Uth[(size_t)rp * NPOST + nbase + n4]);
    }
#pragma unroll
    for (int p = 0; p < 2; p++) {
        int idx = tid + p * 256, row = idx >> 2, c4 = (idx & 3) * 4;
        *reinterpret_cast<uint4*>(&sZ[row * 20 + c4]) =
            *reinterpret_cast<const uint4*>(&g_Zh[(size_t)(b0 + row) * 16 + c4]);
    }

    for (int t = 0; t < 4; t++) {
        const int buf = t & 1;
        const int n0 = nbase + t * 128;
#pragma unroll
        for (int p = 0; p < 2; p++) {
            int idx = tid + p * 256, rp = idx >> 5, n4 = (idx & 31) * 4;
            *reinterpret_cast<uint4*>(&sU[buf][rp * 132 + n4]) = pU[p];
        }
        __syncthreads();   // also covers sZ on t==0

        if (t + 1 < 4) {
#pragma unroll
            for (int p = 0; p < 2; p++) {
                int idx = tid + p * 256, rp = idx >> 5, n4 = (idx & 31) * 4;
                pU[p] = *reinterpret_cast<const uint4*>(
                    &g_Uth[(size_t)rp * NPOST + nbase + (t + 1) * 128 + n4]);
            }
        }

        float acc[4][4][4];
#pragma unroll
        for (int mt = 0; mt < 4; mt++)
#pragma unroll
            for (int nt = 0; nt < 4; nt++)
#pragma unroll
                for (int q = 0; q < 4; q++) acc[mt][nt][q] = 0.f;

#pragma unroll
        for (int ks = 0; ks < 2; ks++) {
            unsigned bf[4][2];
#pragma unroll
            for (int nt = 0; nt < 4; nt++) {
                const int nc = wn * 32 + nt * 8 + gq;
                bf[nt][0] = sU[buf][(ks * 8 + tg) * 132 + nc];
                bf[nt][1] = sU[buf][(ks * 8 + tg + 4) * 132 + nc];
            }
#pragma unroll
            for (int mt = 0; mt < 4; mt++) {
                const unsigned rb = (wm * 64 + mt * 16 + rowoff) * 80 + ks * 32 + segoff;
                unsigned af[4];
                ldsm_x4(af, baseZ + rb);
#pragma unroll
                for (int nt = 0; nt < 4; nt++)
                    mma16(acc[mt][nt], af, bf[nt]);
            }
        }

#pragma unroll
        for (int mt = 0; mt < 4; mt++) {
            const int row = b0 + wm * 64 + mt * 16 + gq;
#pragma unroll
            for (int nt = 0; nt < 4; nt++) {
                const int col = n0 + wn * 32 + nt * 8 + tg * 2;
                *reinterpret_cast<float2*>(&Y[(size_t)row * NPOST + col]) =
                    make_float2(acc[mt][nt][0], acc[mt][nt][1]);
                *reinterpret_cast<float2*>(&Y[(size_t)(row + 8) * NPOST + col]) =
                    make_float2(acc[mt][nt][2], acc[mt][nt][3]);
            }
        }
        __syncthreads();   // subtile buffer handoff
    }
}

// ---------------------------------------------------------------------------
// Entry point. Inputs: spikes, U, V, mask_* (masks unused by the reference).
// ---------------------------------------------------------------------------
extern "C" void kernel_launch(void* const* d_in, const int* in_sizes, int n_in,
                              void* d_out, int out_size) {
    const float* spikes = (const float*)d_in[0];
    const float* U      = (const float*)d_in[1];
    const float* V      = (const float*)d_in[2];
    float* Y            = (float*)d_out;

    prepU<<<65, 256>>>(U);
    gemmA<<<dim3(SPLITK, MT256), 256>>>(spikes, V);
    gemmB<<<dim3(NPOST / 512, B_ / 128), 256>>>(Y);
}